// round 16
// baseline (speedup 1.0000x reference)
#include <cuda_runtime.h>
#include <cstdint>

// Problem dims
#define Bb   4
#define Ss   512
#define Dd   1024
#define Hh   16
#define HDh  64
#define KR   64
#define Mrows (Bb*Ss)          // 2048
#define THREE_D (3*Dd)         // 3072

__device__ __constant__ float kSCALE = 0.125f;   // 1/sqrt(64)
#define ALPHA_F 0.25f

// Scratch (device globals; no allocation allowed)
__device__ float g_qkv[3*Bb*Hh*Ss*HDh];   // [t][b*H+h][s][hd]
__device__ float g_ks [Bb*Hh*Ss*HDh];     // smoothed K
__device__ float g_vs [Bb*Hh*Ss*HDh];     // smoothed V
__device__ float g_attnout[Bb*Ss*Dd];     // [B*S, D]

// packed fp32x2 FMA (Blackwell FFMA2; PTX-only encoding)
#define FMA2(d, a, b) \
    asm("fma.rn.f32x2 %0, %1, %2, %0;" : "+l"(d) : "l"(a), "l"(b))

__device__ __forceinline__ unsigned long long dup_f32(float v) {
    unsigned long long r;
    asm("mov.b64 %0, {%1, %1};" : "=l"(r) : "f"(v));
    return r;
}

// ---------------------------------------------------------------------------
// Tiled fp32 GEMM on packed f32x2: C[M,N] = A[M,K] @ B[K,N] + bias[N]
// BM=BN=128, BK=32, TM=8, TN=8 (4 packed N-pairs), 256 threads.
// (unchanged from R14 — known good)
// ---------------------------------------------------------------------------
template<bool QKV_SCATTER, bool A_FROM_ATTN>
__global__ __launch_bounds__(256, 1) void sgemm2_k(
    int M, int N, int Kd,
    const float* __restrict__ Ain, const float* __restrict__ Bm,
    const float* __restrict__ bias, float* __restrict__ C)
{
    __shared__ float As[32][128];   // [k][m] transposed
    __shared__ float Bs[32][128];   // [k][n]

    const int tid = threadIdx.x;
    const int cCol = blockIdx.x;   // N tile
    const int cRow = blockIdx.y;   // M tile

    const float* A = (A_FROM_ATTN ? (const float*)g_attnout : Ain) + (size_t)cRow*128*Kd;
    const float* Bp = Bm + cCol*128;

    // A loading: 2 threads per row, 4 consecutive float4 each (16 floats)
    const int aRow = tid >> 1;             // 0..127
    const int aCol = (tid & 1) * 16;       // float base col: 0 or 16
    // B loading: 4 rows per thread (stride 8), 1 float4 each
    const int bRow = tid >> 5;             // 0..7
    const int bCol = tid & 31;             // float4 col

    const int threadCol = tid & 15;        // 0..15
    const int threadRow = tid >> 4;        // 0..15

    unsigned long long acc[8][4];
    #pragma unroll
    for (int i = 0; i < 8; i++)
        #pragma unroll
        for (int j = 0; j < 4; j++) acc[i][j] = 0ull;   // (0.0f, 0.0f)

    // prefetch first tile into registers
    float4 pA[4], pB[4];
    #pragma unroll
    for (int j = 0; j < 4; j++) {
        pA[j] = *(const float4*)(&A[(size_t)aRow*Kd + aCol + j*4]);
        pB[j] = *(const float4*)(&Bp[(size_t)(bRow + 8*j)*N + bCol*4]);
    }

    for (int kt = 32; kt <= Kd; kt += 32) {
        // stage A transposed (scalar STS) and B (STS.128)
        #pragma unroll
        for (int j = 0; j < 4; j++) {
            const int kk = aCol + j*4;
            As[kk+0][aRow] = pA[j].x;
            As[kk+1][aRow] = pA[j].y;
            As[kk+2][aRow] = pA[j].z;
            As[kk+3][aRow] = pA[j].w;
            *(float4*)(&Bs[bRow + 8*j][bCol*4]) = pB[j];
        }
        __syncthreads();

        if (kt < Kd) {   // prefetch next tile
            #pragma unroll
            for (int j = 0; j < 4; j++) {
                pA[j] = *(const float4*)(&A[(size_t)aRow*Kd + kt + aCol + j*4]);
                pB[j] = *(const float4*)(&Bp[(size_t)(kt + bRow + 8*j)*N + bCol*4]);
            }
        }

        #pragma unroll
        for (int dot = 0; dot < 32; ++dot) {
            // A: 8 floats, 2 LDS.128 (16-lane broadcast), dup to pairs in regs
            float4 a0 = *(const float4*)&As[dot][threadRow*8];
            float4 a1 = *(const float4*)&As[dot][threadRow*8 + 4];
            unsigned long long rm[8];
            rm[0] = dup_f32(a0.x); rm[1] = dup_f32(a0.y);
            rm[2] = dup_f32(a0.z); rm[3] = dup_f32(a0.w);
            rm[4] = dup_f32(a1.x); rm[5] = dup_f32(a1.y);
            rm[6] = dup_f32(a1.z); rm[7] = dup_f32(a1.w);
            // B: natural (n0,n1) pairs, 2 LDS.128
            ulonglong2 b0 = *(const ulonglong2*)&Bs[dot][threadCol*8];
            ulonglong2 b1 = *(const ulonglong2*)&Bs[dot][threadCol*8 + 4];
            unsigned long long rn[4] = {b0.x, b0.y, b1.x, b1.y};
            #pragma unroll
            for (int i = 0; i < 8; i++) {
                FMA2(acc[i][0], rm[i], rn[0]);
                FMA2(acc[i][1], rm[i], rn[1]);
                FMA2(acc[i][2], rm[i], rn[2]);
                FMA2(acc[i][3], rm[i], rn[3]);
            }
        }
        __syncthreads();
    }

    // epilogue: acc[i][j] packs columns (threadCol*8+2j, +2j+1) for row threadRow*8+i
    #pragma unroll
    for (int i = 0; i < 8; i++) {
        const int m = cRow*128 + threadRow*8 + i;
        #pragma unroll
        for (int j = 0; j < 4; j++) {
            const float2 v = *(const float2*)&acc[i][j];
            const int n0 = cCol*128 + threadCol*8 + 2*j;
            if (QKV_SCATTER) {
                const int b  = m >> 9;
                const int s  = m & 511;
                #pragma unroll
                for (int e = 0; e < 2; e++) {
                    const int n  = n0 + e;
                    const float val = (e ? v.y : v.x) + bias[n];
                    const int t  = n >> 10;
                    const int h  = (n >> 6) & 15;
                    const int hd = n & 63;
                    const int bh = b*Hh + h;
                    g_qkv[(((size_t)t*Bb*Hh + bh)*Ss + s)*HDh + hd] = val;
                }
            } else {
                *(float2*)&C[(size_t)m*N + n0] =
                    make_float2(v.x + bias[n0], v.y + bias[n0+1]);
            }
        }
    }
}

// ---------------------------------------------------------------------------
// Neighbor smoothing: k_s[j] = (1-a)k[j] + a/2 (k[clip(j-1)] + k[clip(j+1)])
// ---------------------------------------------------------------------------
__global__ __launch_bounds__(256) void smooth_kernel()
{
    const int idx = blockIdx.x*blockDim.x + threadIdx.x;
    const int total = Bb*Hh*Ss*16;
    if (idx >= total) return;
    const int f  = idx & 15;
    const int s  = (idx >> 4) & (Ss-1);
    const int bh = idx >> 13;

    const float4* qkv4 = (const float4*)g_qkv;
    const float w0 = 1.0f - ALPHA_F;
    const float w1 = ALPHA_F * 0.5f;
    const int dl = (s > 0)    ? -16 : 0;
    const int dr = (s < Ss-1) ?  16 : 0;

    {
        const int base = (((Bb*Hh) + bh)*Ss + s)*16 + f;
        float4 c = qkv4[base], l = qkv4[base+dl], r = qkv4[base+dr];
        float4 o;
        o.x = w0*c.x + w1*(l.x + r.x);
        o.y = w0*c.y + w1*(l.y + r.y);
        o.z = w0*c.z + w1*(l.z + r.z);
        o.w = w0*c.w + w1*(l.w + r.w);
        ((float4*)g_ks)[(bh*Ss + s)*16 + f] = o;
    }
    {
        const int base = (((2*Bb*Hh) + bh)*Ss + s)*16 + f;
        float4 c = qkv4[base], l = qkv4[base+dl], r = qkv4[base+dr];
        float4 o;
        o.x = w0*c.x + w1*(l.x + r.x);
        o.y = w0*c.y + w1*(l.y + r.y);
        o.z = w0*c.z + w1*(l.z + r.z);
        o.w = w0*c.w + w1*(l.w + r.w);
        ((float4*)g_vs)[(bh*Ss + s)*16 + f] = o;
    }
}

// ---------------------------------------------------------------------------
// Routed attention: one warp per query (b,h,s).
// CAUSAL SKIP: masked routes (r > s) have softmax weight exactly 0.0f
// (exp(-1e9 - mx) underflows; self-route keeps mx finite), so we skip their
// K dot (per-lane predication — no LDG issued) and their V row entirely
// (warp-uniform branch on the broadcast weight). ~Halves L2 gather traffic;
// bit-identical result.
// ---------------------------------------------------------------------------
__global__ __launch_bounds__(256) void attn_kernel(const int* __restrict__ routes)
{
    __shared__ float qs    [8][64];
    __shared__ float attn_s[8][64];
    __shared__ int   rt_s  [8][64];

    const int warp = threadIdx.x >> 5;
    const int lane = threadIdx.x & 31;
    const int gq = blockIdx.x*8 + warp;      // (b*H + h)*S + s
    const int s  = gq & (Ss-1);
    const int bh = gq >> 9;

    const float* qrow = g_qkv + ((size_t)bh*Ss + s)*HDh;   // t=0
    const float* kb   = g_ks + (size_t)bh*Ss*HDh;
    const float* vb   = g_vs + (size_t)bh*Ss*HDh;

    if (lane < 16)
        ((float4*)qs[warp])[lane] = ((const float4*)qrow)[lane];
    const int r0 = routes[s*KR + lane];
    const int r1 = routes[s*KR + 32 + lane];
    rt_s[warp][lane]      = r0;
    rt_s[warp][lane + 32] = r1;
    __syncwarp();

    const float4* q4 = (const float4*)qs[warp];

    // Phase 1: scores — skip K loads for masked routes (r > s)
    float sc0 = -1e9f, sc1 = -1e9f;
    if (r0 <= s) {
        const float4* k0 = (const float4*)(kb + r0*HDh);
        float a0 = 0.f;
        #pragma unroll
        for (int d = 0; d < 16; ++d) {
            float4 qv = q4[d];
            float4 x0 = k0[d];
            a0 += qv.x*x0.x + qv.y*x0.y + qv.z*x0.z + qv.w*x0.w;
        }
        sc0 = a0 * kSCALE;
    }
    if (r1 <= s) {
        const float4* k1 = (const float4*)(kb + r1*HDh);
        float a1 = 0.f;
        #pragma unroll
        for (int d = 0; d < 16; ++d) {
            float4 qv = q4[d];
            float4 x1 = k1[d];
            a1 += qv.x*x1.x + qv.y*x1.y + qv.z*x1.z + qv.w*x1.w;
        }
        sc1 = a1 * kSCALE;
    }

    // softmax across warp
    float mx = fmaxf(sc0, sc1);
    #pragma unroll
    for (int o = 16; o > 0; o >>= 1)
        mx = fmaxf(mx, __shfl_xor_sync(0xffffffffu, mx, o));
    float e0 = __expf(sc0 - mx);   // exactly 0.0f for masked routes
    float e1 = __expf(sc1 - mx);
    float sum = e0 + e1;
    #pragma unroll
    for (int o = 16; o > 0; o >>= 1)
        sum += __shfl_xor_sync(0xffffffffu, sum, o);
    const float inv = 1.0f / sum;
    attn_s[warp][lane]      = e0 * inv;
    attn_s[warp][lane + 32] = e1 * inv;
    __syncwarp();

    // Phase 2: V accumulate — warp-uniform skip of zero-weight routes
    float o0 = 0.f, o1 = 0.f;
    #pragma unroll 4
    for (int j = 0; j < KR; ++j) {
        const float w = attn_s[warp][j];   // uniform across lanes (smem bcast)
        if (w != 0.f) {
            const int rj = rt_s[warp][j];
            const float2 vv = *(const float2*)(vb + rj*HDh + 2*lane);
            o0 += w*vv.x;
            o1 += w*vv.y;
        }
    }

    const int b = bh >> 4;
    const int h = bh & 15;
    float2* op = (float2*)(g_attnout + ((size_t)(b*Ss + s))*Dd + h*HDh) + lane;
    *op = make_float2(o0, o1);
}

// ---------------------------------------------------------------------------
extern "C" void kernel_launch(void* const* d_in, const int* in_sizes, int n_in,
                              void* d_out, int out_size)
{
    const float* x      = (const float*)d_in[0];   // [B,S,D]
    const float* w_qkv  = (const float*)d_in[1];   // [D, 3D]
    const float* b_qkv  = (const float*)d_in[2];   // [3D]
    const float* w_out  = (const float*)d_in[3];   // [D, D]
    const float* b_out  = (const float*)d_in[4];   // [D]
    const int*   routes = (const int*)d_in[5];     // [S, K]
    float* out = (float*)d_out;                    // [B,S,D]

    // 1) QKV projection + scatter into [t][bh][s][hd]
    {
        dim3 grid(THREE_D/128, Mrows/128);         // (24, 16)
        sgemm2_k<true, false><<<grid, 256>>>(Mrows, THREE_D, Dd, x, w_qkv, b_qkv, nullptr);
    }
    // 2) neighbor smoothing of K/V
    {
        const int total = Bb*Hh*Ss*16;
        smooth_kernel<<<(total + 255)/256, 256>>>();
    }
    // 3) routed attention -> g_attnout [B*S, D]
    {
        attn_kernel<<<(Bb*Hh*Ss)/8, 256>>>(routes);
    }
    // 4) output projection
    {
        dim3 grid(Dd/128, Mrows/128);              // (8, 16)
        sgemm2_k<false, true><<<grid, 256>>>(Mrows, Dd, Dd, nullptr, w_out, b_out, out);
    }
}

// round 17
// speedup vs baseline: 1.6393x; 1.6393x over previous
#include <cuda_runtime.h>
#include <cstdint>

// Problem dims
#define Bb   4
#define Ss   512
#define Dd   1024
#define Hh   16
#define HDh  64
#define KR   64
#define Mrows (Bb*Ss)          // 2048
#define THREE_D (3*Dd)         // 3072

__device__ __constant__ float kSCALE = 0.125f;   // 1/sqrt(64)
#define ALPHA_F 0.25f

// Scratch (device globals; no allocation allowed)
__device__ float g_qkv[3*Bb*Hh*Ss*HDh];   // [t][b*H+h][s][hd]
__device__ float g_ks [Bb*Hh*Ss*HDh];     // smoothed K
__device__ float g_vs [Bb*Hh*Ss*HDh];     // smoothed V
__device__ float g_attnout[Bb*Ss*Dd];     // [B*S, D]

// packed fp32x2 FMA (Blackwell FFMA2; PTX-only encoding)
#define FMA2(d, a, b) \
    asm("fma.rn.f32x2 %0, %1, %2, %0;" : "+l"(d) : "l"(a), "l"(b))

__device__ __forceinline__ unsigned long long dup_f32(float v) {
    unsigned long long r;
    asm("mov.b64 %0, {%1, %1};" : "=l"(r) : "f"(v));
    return r;
}

// ---------------------------------------------------------------------------
// Tiled fp32 GEMM on packed f32x2: C[M,N] = A[M,K] @ B[K,N] + bias[N]
// BM=BN=128, BK=32, TM=8, TN=8 (4 packed N-pairs), 256 threads.
// (byte-identical to the 590.2us R14/R15 version — known good)
// ---------------------------------------------------------------------------
template<bool QKV_SCATTER, bool A_FROM_ATTN>
__global__ __launch_bounds__(256, 1) void sgemm2_k(
    int M, int N, int Kd,
    const float* __restrict__ Ain, const float* __restrict__ Bm,
    const float* __restrict__ bias, float* __restrict__ C)
{
    __shared__ float As[32][128];   // [k][m] transposed
    __shared__ float Bs[32][128];   // [k][n]

    const int tid = threadIdx.x;
    const int cCol = blockIdx.x;   // N tile
    const int cRow = blockIdx.y;   // M tile

    const float* A = (A_FROM_ATTN ? (const float*)g_attnout : Ain) + (size_t)cRow*128*Kd;
    const float* Bp = Bm + cCol*128;

    // A loading: 2 threads per row, 4 consecutive float4 each (16 floats)
    const int aRow = tid >> 1;             // 0..127
    const int aCol = (tid & 1) * 16;       // float base col: 0 or 16
    // B loading: 4 rows per thread (stride 8), 1 float4 each
    const int bRow = tid >> 5;             // 0..7
    const int bCol = tid & 31;             // float4 col

    const int threadCol = tid & 15;        // 0..15
    const int threadRow = tid >> 4;        // 0..15

    unsigned long long acc[8][4];
    #pragma unroll
    for (int i = 0; i < 8; i++)
        #pragma unroll
        for (int j = 0; j < 4; j++) acc[i][j] = 0ull;   // (0.0f, 0.0f)

    // prefetch first tile into registers
    float4 pA[4], pB[4];
    #pragma unroll
    for (int j = 0; j < 4; j++) {
        pA[j] = *(const float4*)(&A[(size_t)aRow*Kd + aCol + j*4]);
        pB[j] = *(const float4*)(&Bp[(size_t)(bRow + 8*j)*N + bCol*4]);
    }

    for (int kt = 32; kt <= Kd; kt += 32) {
        // stage A transposed (scalar STS) and B (STS.128)
        #pragma unroll
        for (int j = 0; j < 4; j++) {
            const int kk = aCol + j*4;
            As[kk+0][aRow] = pA[j].x;
            As[kk+1][aRow] = pA[j].y;
            As[kk+2][aRow] = pA[j].z;
            As[kk+3][aRow] = pA[j].w;
            *(float4*)(&Bs[bRow + 8*j][bCol*4]) = pB[j];
        }
        __syncthreads();

        if (kt < Kd) {   // prefetch next tile
            #pragma unroll
            for (int j = 0; j < 4; j++) {
                pA[j] = *(const float4*)(&A[(size_t)aRow*Kd + kt + aCol + j*4]);
                pB[j] = *(const float4*)(&Bp[(size_t)(kt + bRow + 8*j)*N + bCol*4]);
            }
        }

        #pragma unroll
        for (int dot = 0; dot < 32; ++dot) {
            // A: 8 floats, 2 LDS.128 (16-lane broadcast), dup to pairs in regs
            float4 a0 = *(const float4*)&As[dot][threadRow*8];
            float4 a1 = *(const float4*)&As[dot][threadRow*8 + 4];
            unsigned long long rm[8];
            rm[0] = dup_f32(a0.x); rm[1] = dup_f32(a0.y);
            rm[2] = dup_f32(a0.z); rm[3] = dup_f32(a0.w);
            rm[4] = dup_f32(a1.x); rm[5] = dup_f32(a1.y);
            rm[6] = dup_f32(a1.z); rm[7] = dup_f32(a1.w);
            // B: natural (n0,n1) pairs, 2 LDS.128
            ulonglong2 b0 = *(const ulonglong2*)&Bs[dot][threadCol*8];
            ulonglong2 b1 = *(const ulonglong2*)&Bs[dot][threadCol*8 + 4];
            unsigned long long rn[4] = {b0.x, b0.y, b1.x, b1.y};
            #pragma unroll
            for (int i = 0; i < 8; i++) {
                FMA2(acc[i][0], rm[i], rn[0]);
                FMA2(acc[i][1], rm[i], rn[1]);
                FMA2(acc[i][2], rm[i], rn[2]);
                FMA2(acc[i][3], rm[i], rn[3]);
            }
        }
        __syncthreads();
    }

    // epilogue: acc[i][j] packs columns (threadCol*8+2j, +2j+1) for row threadRow*8+i
    #pragma unroll
    for (int i = 0; i < 8; i++) {
        const int m = cRow*128 + threadRow*8 + i;
        #pragma unroll
        for (int j = 0; j < 4; j++) {
            const float2 v = *(const float2*)&acc[i][j];
            const int n0 = cCol*128 + threadCol*8 + 2*j;
            if (QKV_SCATTER) {
                const int b  = m >> 9;
                const int s  = m & 511;
                #pragma unroll
                for (int e = 0; e < 2; e++) {
                    const int n  = n0 + e;
                    const float val = (e ? v.y : v.x) + bias[n];
                    const int t  = n >> 10;
                    const int h  = (n >> 6) & 15;
                    const int hd = n & 63;
                    const int bh = b*Hh + h;
                    g_qkv[(((size_t)t*Bb*Hh + bh)*Ss + s)*HDh + hd] = val;
                }
            } else {
                *(float2*)&C[(size_t)m*N + n0] =
                    make_float2(v.x + bias[n0], v.y + bias[n0+1]);
            }
        }
    }
}

// ---------------------------------------------------------------------------
// Neighbor smoothing: k_s[j] = (1-a)k[j] + a/2 (k[clip(j-1)] + k[clip(j+1)])
// ---------------------------------------------------------------------------
__global__ __launch_bounds__(256) void smooth_kernel()
{
    const int idx = blockIdx.x*blockDim.x + threadIdx.x;
    const int total = Bb*Hh*Ss*16;
    if (idx >= total) return;
    const int f  = idx & 15;
    const int s  = (idx >> 4) & (Ss-1);
    const int bh = idx >> 13;

    const float4* qkv4 = (const float4*)g_qkv;
    const float w0 = 1.0f - ALPHA_F;
    const float w1 = ALPHA_F * 0.5f;
    const int dl = (s > 0)    ? -16 : 0;
    const int dr = (s < Ss-1) ?  16 : 0;

    {
        const int base = (((Bb*Hh) + bh)*Ss + s)*16 + f;
        float4 c = qkv4[base], l = qkv4[base+dl], r = qkv4[base+dr];
        float4 o;
        o.x = w0*c.x + w1*(l.x + r.x);
        o.y = w0*c.y + w1*(l.y + r.y);
        o.z = w0*c.z + w1*(l.z + r.z);
        o.w = w0*c.w + w1*(l.w + r.w);
        ((float4*)g_ks)[(bh*Ss + s)*16 + f] = o;
    }
    {
        const int base = (((2*Bb*Hh) + bh)*Ss + s)*16 + f;
        float4 c = qkv4[base], l = qkv4[base+dl], r = qkv4[base+dr];
        float4 o;
        o.x = w0*c.x + w1*(l.x + r.x);
        o.y = w0*c.y + w1*(l.y + r.y);
        o.z = w0*c.z + w1*(l.z + r.z);
        o.w = w0*c.w + w1*(l.w + r.w);
        ((float4*)g_vs)[(bh*Ss + s)*16 + f] = o;
    }
}

// ---------------------------------------------------------------------------
// Routed attention: one warp per query (b,h,s).
// BALLOT COMPACTION: active routes (r <= s) are compacted to the front of
// rt_s via warp ballot/popc prefix BEFORE any loads. Phase 1 dots are
// unconditional (lanes past n_act duplicate the last active row — their
// loads coalesce with that lane's, so they're free) with the score masked by
// a select. Phase 2 loops to the warp-uniform n_act: no branches in the
// load stream, full MLP, ~half the distinct L2 gather traffic.
// ---------------------------------------------------------------------------
__global__ __launch_bounds__(256) void attn_kernel(const int* __restrict__ routes)
{
    __shared__ float qs    [8][64];
    __shared__ float attn_s[8][64];
    __shared__ int   rt_s  [8][64];

    const int warp = threadIdx.x >> 5;
    const int lane = threadIdx.x & 31;
    const int gq = blockIdx.x*8 + warp;      // (b*H + h)*S + s
    const int s  = gq & (Ss-1);
    const int bh = gq >> 9;

    const float* qrow = g_qkv + ((size_t)bh*Ss + s)*HDh;   // t=0
    const float* kb   = g_ks + (size_t)bh*Ss*HDh;
    const float* vb   = g_vs + (size_t)bh*Ss*HDh;

    if (lane < 16)
        ((float4*)qs[warp])[lane] = ((const float4*)qrow)[lane];

    // compact active routes to the front of rt_s
    const int r0 = routes[s*KR + lane];
    const int r1 = routes[s*KR + 32 + lane];
    const bool a0 = (r0 <= s);
    const bool a1 = (r1 <= s);
    const uint32_t bal0 = __ballot_sync(0xffffffffu, a0);
    const uint32_t bal1 = __ballot_sync(0xffffffffu, a1);
    const int n0 = __popc(bal0);
    const int n_act = n0 + __popc(bal1);          // >= 1 (self-route)
    const uint32_t lmask = (1u << lane) - 1u;
    if (a0) rt_s[warp][__popc(bal0 & lmask)]      = r0;   // predicated STS
    if (a1) rt_s[warp][n0 + __popc(bal1 & lmask)] = r1;
    __syncwarp();

    const float4* q4 = (const float4*)qs[warp];

    // Phase 1: dots on compacted routes; lanes past n_act duplicate the last
    // active row (loads coalesce) and get score -1e9 via select (no branch).
    const int last = n_act - 1;
    const int i0 = lane;
    const int i1 = lane + 32;
    const int c0 = rt_s[warp][i0 < last ? i0 : last];
    const int c1 = rt_s[warp][i1 < last ? i1 : last];
    const float4* k0 = (const float4*)(kb + c0*HDh);
    const float4* k1 = (const float4*)(kb + c1*HDh);
    float d0 = 0.f, d1 = 0.f;
    #pragma unroll
    for (int d = 0; d < 16; ++d) {
        float4 qv = q4[d];
        float4 x0 = k0[d];
        float4 x1 = k1[d];
        d0 += qv.x*x0.x + qv.y*x0.y + qv.z*x0.z + qv.w*x0.w;
        d1 += qv.x*x1.x + qv.y*x1.y + qv.z*x1.z + qv.w*x1.w;
    }
    float sc0 = (i0 < n_act) ? d0 * kSCALE : -1e9f;
    float sc1 = (i1 < n_act) ? d1 * kSCALE : -1e9f;

    // softmax across warp (inactive slots underflow to exactly 0)
    float mx = fmaxf(sc0, sc1);
    #pragma unroll
    for (int o = 16; o > 0; o >>= 1)
        mx = fmaxf(mx, __shfl_xor_sync(0xffffffffu, mx, o));
    float e0 = __expf(sc0 - mx);
    float e1 = __expf(sc1 - mx);
    float sum = e0 + e1;
    #pragma unroll
    for (int o = 16; o > 0; o >>= 1)
        sum += __shfl_xor_sync(0xffffffffu, sum, o);
    const float inv = 1.0f / sum;
    attn_s[warp][i0] = e0 * inv;
    attn_s[warp][i1] = e1 * inv;
    __syncwarp();

    // Phase 2: V accumulate over warp-uniform n_act (no divergence, batched loads)
    float o0 = 0.f, o1 = 0.f;
    #pragma unroll 4
    for (int j = 0; j < n_act; ++j) {
        const int   rj = rt_s[warp][j];
        const float w  = attn_s[warp][j];
        const float2 vv = *(const float2*)(vb + rj*HDh + 2*lane);
        o0 += w*vv.x;
        o1 += w*vv.y;
    }

    const int b = bh >> 4;
    const int h = bh & 15;
    float2* op = (float2*)(g_attnout + ((size_t)(b*Ss + s))*Dd + h*HDh) + lane;
    *op = make_float2(o0, o1);
}

// ---------------------------------------------------------------------------
extern "C" void kernel_launch(void* const* d_in, const int* in_sizes, int n_in,
                              void* d_out, int out_size)
{
    const float* x      = (const float*)d_in[0];   // [B,S,D]
    const float* w_qkv  = (const float*)d_in[1];   // [D, 3D]
    const float* b_qkv  = (const float*)d_in[2];   // [3D]
    const float* w_out  = (const float*)d_in[3];   // [D, D]
    const float* b_out  = (const float*)d_in[4];   // [D]
    const int*   routes = (const int*)d_in[5];     // [S, K]
    float* out = (float*)d_out;                    // [B,S,D]

    // 1) QKV projection + scatter into [t][bh][s][hd]
    {
        dim3 grid(THREE_D/128, Mrows/128);         // (24, 16)
        sgemm2_k<true, false><<<grid, 256>>>(Mrows, THREE_D, Dd, x, w_qkv, b_qkv, nullptr);
    }
    // 2) neighbor smoothing of K/V
    {
        const int total = Bb*Hh*Ss*16;
        smooth_kernel<<<(total + 255)/256, 256>>>();
    }
    // 3) routed attention -> g_attnout [B*S, D]
    {
        attn_kernel<<<(Bb*Hh*Ss)/8, 256>>>(routes);
    }
    // 4) output projection
    {
        dim3 grid(Dd/128, Mrows/128);              // (8, 16)
        sgemm2_k<false, true><<<grid, 256>>>(Mrows, Dd, Dd, nullptr, w_out, b_out, out);
    }
}